// round 13
// baseline (speedup 1.0000x reference)
#include <cuda_runtime.h>
#include <math.h>

#define NMAX 100000
#define EMAX 1600000
#define C_IN 64
#define C_OUT 128
#define GRPB 32                      // gemm rows per block
#define NB_SCAN ((NMAX + 1023) / 1024)

// Scratch (device globals — no allocations allowed)
__device__ float g_y[(size_t)NMAX * C_IN];
__device__ float g_x0[(size_t)NMAX * C_IN];
__device__ float g_x1[(size_t)NMAX * C_IN];
__device__ float g_dinv[NMAX];
__device__ int   g_cnt[NMAX];        // must be 0 at entry of every call (invariant)
__device__ int   g_fillctr[NMAX];
__device__ int   g_rowstart[NMAX + 1];
__device__ int2  g_edge[EMAX];       // {srcid, coef bits}
__device__ int   g_blocksum[NB_SCAN];
__device__ int   g_flag[NB_SCAN];    // must be 0 at entry (reset by fill_kernel)
__device__ int   g_bar_arrive;
__device__ int   g_bar_depart;

__device__ __forceinline__ int clampi(int v, int lo, int hi) {
    return v < lo ? lo : (v > hi ? hi : v);
}

// ---- f32x2 packed math helpers ----
__device__ __forceinline__ unsigned long long pack2(float lo, float hi) {
    unsigned long long r;
    asm("mov.b64 %0, {%1, %2};" : "=l"(r) : "f"(lo), "f"(hi));
    return r;
}
__device__ __forceinline__ void unpack2(unsigned long long v, float& lo, float& hi) {
    asm("mov.b64 {%0, %1}, %2;" : "=f"(lo), "=f"(hi) : "l"(v));
}
#define FMA_F32X2(d, a, b, c) \
    asm("fma.rn.f32x2 %0, %1, %2, %3;" : "=l"(d) : "l"(a), "l"(b), "l"(c))

// self-resetting grid barrier (all nb blocks resident)
__device__ __forceinline__ void grid_barrier(int nb) {
    __syncthreads();
    if (threadIdx.x == 0) {
        __threadfence();
        atomicAdd(&g_bar_arrive, 1);
        while (atomicAdd(&g_bar_arrive, 0) < nb) { }
        int d = atomicAdd(&g_bar_depart, 1);
        if (d == nb - 1) {
            g_bar_arrive = 0;
            g_bar_depart = 0;
            __threadfence();
        }
    }
    __syncthreads();
}

// ---------------- launch 1: count + scan (fused, persistent) ---------------
__global__ void __launch_bounds__(1024) csr_scan_kernel(
        const int* __restrict__ dst, int e, int n, int nb) {
    for (int i = blockIdx.x * 1024 + threadIdx.x; i < e; i += nb * 1024)
        atomicAdd(&g_cnt[clampi(dst[i], 0, n - 1)], 1);

    grid_barrier(nb);

    __shared__ int sm[1024];
    __shared__ int prefix_sm;
    const int b = blockIdx.x;
    const int i = b * 1024 + threadIdx.x;

    int v = (i < n) ? g_cnt[i] : 0;
    sm[threadIdx.x] = v;
    __syncthreads();
    #pragma unroll
    for (int off = 1; off < 1024; off <<= 1) {
        int t = (threadIdx.x >= off) ? sm[threadIdx.x - off] : 0;
        __syncthreads();
        sm[threadIdx.x] += t;
        __syncthreads();
    }
    const int total = sm[1023];

    if (threadIdx.x == 0) {
        prefix_sm = 0;
        g_blocksum[b] = total;
        __threadfence();
        atomicExch(&g_flag[b], 1);
    }
    __syncthreads();

    int local = 0;
    for (int p = threadIdx.x; p < b; p += 1024) {
        while (atomicAdd(&g_flag[p], 0) == 0) { }
        local += g_blocksum[p];
    }
    if (local) atomicAdd(&prefix_sm, local);
    __syncthreads();
    const int prefix = prefix_sm;

    if (i < n) {
        int rs = prefix + sm[threadIdx.x] - v;
        g_rowstart[i] = rs;
        g_fillctr[i]  = rs;
        g_dinv[i]     = rsqrtf((float)v + 1.0f);
        g_cnt[i]      = 0;
    }
    if (b == nb - 1 && threadIdx.x == 0) g_rowstart[n] = prefix + total;
}

// ---------------- launch 2: fill edges (and reset lookback flags) ---------
__global__ void fill_kernel(const int* __restrict__ src,
                            const int* __restrict__ dst, int e, int n, int nb) {
    int i = blockIdx.x * blockDim.x + threadIdx.x;
    if (i < nb) g_flag[i] = 0;
    if (i >= e) return;
    int s = clampi(src[i], 0, n - 1);
    int d = clampi(dst[i], 0, n - 1);
    int pos = atomicAdd(&g_fillctr[d], 1);
    g_edge[pos] = make_int2(s, __float_as_int(g_dinv[s] * g_dinv[d]));
}

// ---------------- aggregate in x-space (64 ch) ----------------
__global__ void __launch_bounds__(256)
agg_kernel(const float* __restrict__ xin, int n) {
    int node = (blockIdx.x * blockDim.x + threadIdx.x) >> 5;
    if (node >= n) return;
    int lane = threadIdx.x & 31;
    int half = lane >> 4;
    int hl = lane & 15;

    const float4* x4 = reinterpret_cast<const float4*>(xin);
    float4 acc = make_float4(0.f, 0.f, 0.f, 0.f);

    int e0 = g_rowstart[node];
    int e1 = g_rowstart[node + 1];
    #pragma unroll 4
    for (int t = e0 + half; t < e1; t += 2) {
        int2 ed = __ldg(&g_edge[t]);
        float c = __int_as_float(ed.y);
        float4 v = __ldg(&x4[(size_t)ed.x * 16 + hl]);
        acc.x = fmaf(v.x, c, acc.x);
        acc.y = fmaf(v.y, c, acc.y);
        acc.z = fmaf(v.z, c, acc.z);
        acc.w = fmaf(v.w, c, acc.w);
    }
    __syncwarp();
    acc.x += __shfl_xor_sync(0xffffffffu, acc.x, 16);
    acc.y += __shfl_xor_sync(0xffffffffu, acc.y, 16);
    acc.z += __shfl_xor_sync(0xffffffffu, acc.z, 16);
    acc.w += __shfl_xor_sync(0xffffffffu, acc.w, 16);

    if (half == 0) {
        float dv = g_dinv[node], s2 = dv * dv;
        float4 xs = __ldg(&x4[(size_t)node * 16 + hl]);
        acc.x = fmaf(xs.x, s2, acc.x);
        acc.y = fmaf(xs.y, s2, acc.y);
        acc.z = fmaf(xs.z, s2, acc.z);
        acc.w = fmaf(xs.w, s2, acc.w);
        reinterpret_cast<float4*>(g_y)[(size_t)node * 16 + hl] = acc;
    }
}

// ---------------- outer-product packed GEMM + bias + GLU + residual -------
// 256 threads = 16 thr-rows x 16 thr-cols. Thread (ta,tb): rows {2ta, 2ta+1},
// packed cols 4tb..4tb+3 (packed col c pairs output cols (c, c+64)).
// 8 independent f32x2 accumulator chains per thread.
__global__ void __launch_bounds__(256)
gemm_glu_kernel(const float* __restrict__ xin, float* __restrict__ xout,
                const float* __restrict__ W, const float* __restrict__ b,
                int n) {
    __shared__ unsigned long long ysp[GRPB][C_IN];    // 16 KB pack2(y,y)
    __shared__ unsigned long long wsp[C_IN][C_IN];    // 32 KB pack2(W[k][c],W[k][c+64])

    const int t = threadIdx.x;
    const int ta = t >> 4;          // 0..15 -> rows 2ta, 2ta+1
    const int tb = t & 15;          // 0..15 -> packed cols 4tb..4tb+3
    const int row0 = blockIdx.x * GRPB;

    // stage W packed (4096 entries, 16 per thread; coalesced gmem reads)
    #pragma unroll
    for (int idx = t; idx < C_IN * C_IN; idx += 256) {
        int k = idx >> 6, c = idx & 63;
        wsp[k][c] = pack2(W[k * C_OUT + c], W[k * C_OUT + c + 64]);
    }
    // stage y rows packed-dup (2048 entries, 8 per thread)
    #pragma unroll
    for (int idx = t; idx < GRPB * C_IN; idx += 256) {
        int r = idx >> 6, k = idx & 63;
        int row = row0 + r;
        float v = (row < n) ? g_y[(size_t)row * C_IN + k] : 0.0f;
        ysp[r][k] = pack2(v, v);
    }
    __syncthreads();

    unsigned long long acc[2][4];
    #pragma unroll
    for (int r = 0; r < 2; r++)
        #pragma unroll
        for (int c = 0; c < 4; c++) acc[r][c] = 0ull;

    const int r0i = 2 * ta;
    #pragma unroll 4
    for (int k2 = 0; k2 < C_IN / 2; k2++) {
        const int k = 2 * k2;
        // weights for 4 packed cols, 2 k's: 4x LDS.128
        ulonglong2 wa0 = *reinterpret_cast<const ulonglong2*>(&wsp[k][4 * tb]);
        ulonglong2 wa1 = *reinterpret_cast<const ulonglong2*>(&wsp[k][4 * tb + 2]);
        ulonglong2 wb0 = *reinterpret_cast<const ulonglong2*>(&wsp[k + 1][4 * tb]);
        ulonglong2 wb1 = *reinterpret_cast<const ulonglong2*>(&wsp[k + 1][4 * tb + 2]);
        unsigned long long wk0[4] = {wa0.x, wa0.y, wa1.x, wa1.y};
        unsigned long long wk1[4] = {wb0.x, wb0.y, wb1.x, wb1.y};
        // y for 2 rows, 2 k's: 2x LDS.128
        ulonglong2 y0 = *reinterpret_cast<const ulonglong2*>(&ysp[r0i][k]);
        ulonglong2 y1 = *reinterpret_cast<const ulonglong2*>(&ysp[r0i + 1][k]);
        #pragma unroll
        for (int c = 0; c < 4; c++) {
            FMA_F32X2(acc[0][c], y0.x, wk0[c], acc[0][c]);
            FMA_F32X2(acc[0][c], y0.y, wk1[c], acc[0][c]);
            FMA_F32X2(acc[1][c], y1.x, wk0[c], acc[1][c]);
            FMA_F32X2(acc[1][c], y1.y, wk1[c], acc[1][c]);
        }
    }

    // bias for this thread's 4 packed cols
    float ba[4], bg[4];
    #pragma unroll
    for (int c = 0; c < 4; c++) {
        ba[c] = __ldg(&b[4 * tb + c]);
        bg[c] = __ldg(&b[4 * tb + c + 64]);
    }

    // GLU + residual, float4 stores
    #pragma unroll
    for (int r = 0; r < 2; r++) {
        int row = row0 + r0i + r;
        if (row >= n) break;
        float4 res = *reinterpret_cast<const float4*>(
            &xin[(size_t)row * C_IN + 4 * tb]);
        float o[4];
        #pragma unroll
        for (int c = 0; c < 4; c++) {
            float av, gv;
            unpack2(acc[r][c], av, gv);
            av += ba[c]; gv += bg[c];
            float sig = 1.0f / (1.0f + expf(-gv));
            o[c] = fmaf(av, sig, (&res.x)[c]);
        }
        *reinterpret_cast<float4*>(&xout[(size_t)row * C_IN + 4 * tb]) =
            make_float4(o[0], o[1], o[2], o[3]);
    }
}

extern "C" void kernel_launch(void* const* d_in, const int* in_sizes, int n_in,
                              void* d_out, int out_size) {
    // Identify inputs by SIZE:
    //   x: == out_size (6.4M f32); edge_index: largest rest (3.2M i32);
    //   Ws: next (24576 f32); bs: smallest (384 f32)
    const float* x = nullptr; const float* Ws = nullptr; const float* bs = nullptr;
    const int* ei = nullptr;
    int ei_elems = 0, Ws_elems = 0;
    int used[16] = {0};
    for (int i = 0; i < n_in; i++)
        if (!x && in_sizes[i] == out_size) { x = (const float*)d_in[i]; used[i] = 1; break; }
    {
        int best = -1, bsz = -1;
        for (int i = 0; i < n_in; i++)
            if (!used[i] && in_sizes[i] > bsz) { bsz = in_sizes[i]; best = i; }
        ei = (const int*)d_in[best]; ei_elems = bsz; used[best] = 1;
    }
    {
        int best = -1, bsz = -1;
        for (int i = 0; i < n_in; i++)
            if (!used[i] && in_sizes[i] > bsz) { bsz = in_sizes[i]; best = i; }
        Ws = (const float*)d_in[best]; Ws_elems = bsz; used[best] = 1;
    }
    for (int i = 0; i < n_in; i++)
        if (!used[i]) { bs = (const float*)d_in[i]; used[i] = 1; break; }

    const int n = out_size / C_IN;
    const int e = ei_elems / 2;
    const int L = Ws_elems / (C_IN * C_OUT);
    const int* src = ei;
    const int* dst = ei + e;
    const int nb = (n + 1023) / 1024;   // 98 blocks, all resident

    float *x0, *x1;
    cudaGetSymbolAddress((void**)&x0, g_x0);
    cudaGetSymbolAddress((void**)&x1, g_x1);

    // ---- CSR build: 2 launches ----
    csr_scan_kernel<<<nb, 1024>>>(dst, e, n, nb);
    fill_kernel<<<(e + 255) / 256, 256>>>(src, dst, e, n, nb);

    // ---- layers (gemm of layer 0 is launch 4 -> profiled) ----
    const float* xin = x;
    for (int l = 0; l < L; l++) {
        float* xout = (l == L - 1) ? (float*)d_out : ((l & 1) ? x1 : x0);
        agg_kernel<<<(n * 32 + 255) / 256, 256>>>(xin, n);
        gemm_glu_kernel<<<(n + GRPB - 1) / GRPB, 256>>>(
            xin, xout, Ws + (size_t)l * C_IN * C_OUT, bs + (size_t)l * C_OUT, n);
        xin = xout;
    }
}

// round 14
// speedup vs baseline: 1.5463x; 1.5463x over previous
#include <cuda_runtime.h>
#include <math.h>

#define NMAX 100000
#define EMAX 1600000
#define C_IN 64
#define C_OUT 128
#define GRPB 64                      // gemm rows per block
#define NB_SCAN ((NMAX + 1023) / 1024)

// Scratch (device globals — no allocations allowed)
__device__ float g_y[(size_t)NMAX * C_IN];
__device__ float g_x0[(size_t)NMAX * C_IN];
__device__ float g_x1[(size_t)NMAX * C_IN];
__device__ float g_dinv[NMAX];
__device__ int   g_cnt[NMAX];        // must be 0 at entry of every call (invariant)
__device__ int   g_fillctr[NMAX];
__device__ int   g_rowstart[NMAX + 1];
__device__ int2  g_edge[EMAX];       // {srcid, coef bits}
__device__ int   g_blocksum[NB_SCAN];
__device__ int   g_flag[NB_SCAN];    // must be 0 at entry (reset by fill_kernel)
__device__ int   g_bar_arrive;
__device__ int   g_bar_depart;

__device__ __forceinline__ int clampi(int v, int lo, int hi) {
    return v < lo ? lo : (v > hi ? hi : v);
}

// ---- f32x2 packed math helpers ----
__device__ __forceinline__ unsigned long long pack2(float lo, float hi) {
    unsigned long long r;
    asm("mov.b64 %0, {%1, %2};" : "=l"(r) : "f"(lo), "f"(hi));
    return r;
}
__device__ __forceinline__ void unpack2(unsigned long long v, float& lo, float& hi) {
    asm("mov.b64 {%0, %1}, %2;" : "=f"(lo), "=f"(hi) : "l"(v));
}
#define FMA_F32X2(d, a, b, c) \
    asm("fma.rn.f32x2 %0, %1, %2, %3;" : "=l"(d) : "l"(a), "l"(b), "l"(c))

// self-resetting grid barrier (all nb blocks resident)
__device__ __forceinline__ void grid_barrier(int nb) {
    __syncthreads();
    if (threadIdx.x == 0) {
        __threadfence();
        atomicAdd(&g_bar_arrive, 1);
        while (atomicAdd(&g_bar_arrive, 0) < nb) { }
        int d = atomicAdd(&g_bar_depart, 1);
        if (d == nb - 1) {
            g_bar_arrive = 0;
            g_bar_depart = 0;
            __threadfence();
        }
    }
    __syncthreads();
}

// ---------------- launch 1: count + scan (fused, persistent) ---------------
__global__ void __launch_bounds__(1024) csr_scan_kernel(
        const int* __restrict__ dst, int e, int n, int nb) {
    for (int i = blockIdx.x * 1024 + threadIdx.x; i < e; i += nb * 1024)
        atomicAdd(&g_cnt[clampi(dst[i], 0, n - 1)], 1);

    grid_barrier(nb);

    __shared__ int sm[1024];
    __shared__ int prefix_sm;
    const int b = blockIdx.x;
    const int i = b * 1024 + threadIdx.x;

    int v = (i < n) ? g_cnt[i] : 0;
    sm[threadIdx.x] = v;
    __syncthreads();
    #pragma unroll
    for (int off = 1; off < 1024; off <<= 1) {
        int t = (threadIdx.x >= off) ? sm[threadIdx.x - off] : 0;
        __syncthreads();
        sm[threadIdx.x] += t;
        __syncthreads();
    }
    const int total = sm[1023];

    if (threadIdx.x == 0) {
        prefix_sm = 0;
        g_blocksum[b] = total;
        __threadfence();
        atomicExch(&g_flag[b], 1);
    }
    __syncthreads();

    int local = 0;
    for (int p = threadIdx.x; p < b; p += 1024) {
        while (atomicAdd(&g_flag[p], 0) == 0) { }
        local += g_blocksum[p];
    }
    if (local) atomicAdd(&prefix_sm, local);
    __syncthreads();
    const int prefix = prefix_sm;

    if (i < n) {
        int rs = prefix + sm[threadIdx.x] - v;
        g_rowstart[i] = rs;
        g_fillctr[i]  = rs;
        g_dinv[i]     = rsqrtf((float)v + 1.0f);
        g_cnt[i]      = 0;
    }
    if (b == nb - 1 && threadIdx.x == 0) g_rowstart[n] = prefix + total;
}

// ---------------- launch 2: fill edges (and reset lookback flags) ---------
__global__ void fill_kernel(const int* __restrict__ src,
                            const int* __restrict__ dst, int e, int n, int nb) {
    int i = blockIdx.x * blockDim.x + threadIdx.x;
    if (i < nb) g_flag[i] = 0;
    if (i >= e) return;
    int s = clampi(src[i], 0, n - 1);
    int d = clampi(dst[i], 0, n - 1);
    int pos = atomicAdd(&g_fillctr[d], 1);
    g_edge[pos] = make_int2(s, __float_as_int(g_dinv[s] * g_dinv[d]));
}

// ---------------- aggregate in x-space (64 ch) ----------------
__global__ void __launch_bounds__(256)
agg_kernel(const float* __restrict__ xin, int n) {
    int node = (blockIdx.x * blockDim.x + threadIdx.x) >> 5;
    if (node >= n) return;
    int lane = threadIdx.x & 31;
    int half = lane >> 4;
    int hl = lane & 15;

    const float4* x4 = reinterpret_cast<const float4*>(xin);
    float4 acc = make_float4(0.f, 0.f, 0.f, 0.f);

    int e0 = g_rowstart[node];
    int e1 = g_rowstart[node + 1];
    #pragma unroll 4
    for (int t = e0 + half; t < e1; t += 2) {
        int2 ed = __ldg(&g_edge[t]);
        float c = __int_as_float(ed.y);
        float4 v = __ldg(&x4[(size_t)ed.x * 16 + hl]);
        acc.x = fmaf(v.x, c, acc.x);
        acc.y = fmaf(v.y, c, acc.y);
        acc.z = fmaf(v.z, c, acc.z);
        acc.w = fmaf(v.w, c, acc.w);
    }
    __syncwarp();
    acc.x += __shfl_xor_sync(0xffffffffu, acc.x, 16);
    acc.y += __shfl_xor_sync(0xffffffffu, acc.y, 16);
    acc.z += __shfl_xor_sync(0xffffffffu, acc.z, 16);
    acc.w += __shfl_xor_sync(0xffffffffu, acc.w, 16);

    if (half == 0) {
        float dv = g_dinv[node], s2 = dv * dv;
        float4 xs = __ldg(&x4[(size_t)node * 16 + hl]);
        acc.x = fmaf(xs.x, s2, acc.x);
        acc.y = fmaf(xs.y, s2, acc.y);
        acc.z = fmaf(xs.z, s2, acc.z);
        acc.w = fmaf(xs.w, s2, acc.w);
        reinterpret_cast<float4*>(g_y)[(size_t)node * 16 + hl] = acc;
    }
}

// ---------------- k-split packed GEMM + bias + GLU + residual -------------
// 256 threads = 8 warps; warp w owns rows 8w..8w+7 of the 64-row block.
// Lane owns output cols {2L, 2L+1, 64+2L, 64+2L+1}.
// f32x2 accumulators split over even/odd k (reduced by one add at the end).
// wsp2[k2][c] = (W[2k2][c], W[2k2+1][c]); ysp2 = verbatim f32 row cache.
__global__ void __launch_bounds__(256, 2)
gemm_glu_kernel(const float* __restrict__ xin, float* __restrict__ xout,
                const float* __restrict__ W, const float* __restrict__ b,
                int n) {
    __shared__ __align__(16) unsigned long long wsp2[C_IN / 2][C_OUT]; // 32 KB
    __shared__ __align__(16) unsigned long long ysp2[GRPB][C_IN / 2];  // 16 KB

    const int t = threadIdx.x;
    const int warp = t >> 5;
    const int lane = t & 31;
    const int row0 = blockIdx.x * GRPB;

    // stage W k-pair packed: coalesced (consecutive c per thread group)
    #pragma unroll
    for (int idx = t; idx < (C_IN / 2) * C_OUT; idx += 256) {
        int k2 = idx >> 7, c = idx & 127;
        wsp2[k2][c] = pack2(W[(2 * k2) * C_OUT + c], W[(2 * k2 + 1) * C_OUT + c]);
    }
    // stage y rows verbatim (ulonglong2 = 4 floats)
    {
        const ulonglong2* ysrc = reinterpret_cast<const ulonglong2*>(g_y);
        ulonglong2* ydst = reinterpret_cast<ulonglong2*>(ysp2);
        #pragma unroll
        for (int idx = t; idx < GRPB * (C_IN / 4); idx += 256) {
            int row = row0 + (idx >> 4);
            ydst[idx] = (row < n) ? ysrc[(size_t)row0 * 16 + idx]
                                  : make_ulonglong2(0ull, 0ull);
        }
    }
    __syncthreads();

    unsigned long long aA0[8], aA1[8], aG0[8], aG1[8];
    #pragma unroll
    for (int r = 0; r < 8; r++) { aA0[r] = 0; aA1[r] = 0; aG0[r] = 0; aG1[r] = 0; }

    const int ca = 2 * lane;         // a-cols ca, ca+1; g-cols 64+ca, 64+ca+1
    const int rbase = 8 * warp;

    #pragma unroll 4
    for (int k2 = 0; k2 < C_IN / 2; k2 += 2) {
        // weights for 2 k2's x (2 a-cols + 2 g-cols): 4x LDS.128, full wavefronts
        ulonglong2 wA_0 = *reinterpret_cast<const ulonglong2*>(&wsp2[k2][ca]);
        ulonglong2 wA_1 = *reinterpret_cast<const ulonglong2*>(&wsp2[k2 + 1][ca]);
        ulonglong2 wG_0 = *reinterpret_cast<const ulonglong2*>(&wsp2[k2][64 + ca]);
        ulonglong2 wG_1 = *reinterpret_cast<const ulonglong2*>(&wsp2[k2 + 1][64 + ca]);
        #pragma unroll
        for (int r = 0; r < 8; r++) {
            // y for row, 4 k's: 1x LDS.128 broadcast
            ulonglong2 yv = *reinterpret_cast<const ulonglong2*>(&ysp2[rbase + r][k2]);
            FMA_F32X2(aA0[r], yv.x, wA_0.x, aA0[r]);
            FMA_F32X2(aA0[r], yv.y, wA_1.x, aA0[r]);
            FMA_F32X2(aA1[r], yv.x, wA_0.y, aA1[r]);
            FMA_F32X2(aA1[r], yv.y, wA_1.y, aA1[r]);
            FMA_F32X2(aG0[r], yv.x, wG_0.x, aG0[r]);
            FMA_F32X2(aG0[r], yv.y, wG_1.x, aG0[r]);
            FMA_F32X2(aG1[r], yv.x, wG_0.y, aG1[r]);
            FMA_F32X2(aG1[r], yv.y, wG_1.y, aG1[r]);
        }
    }

    // bias
    const float2* b2 = reinterpret_cast<const float2*>(b);
    float2 bA = __ldg(&b2[lane]);
    float2 bG = __ldg(&b2[32 + lane]);

    // epilogue: k-split reduce + GLU + residual; float2 coalesced per row
    const float2* xin2 = reinterpret_cast<const float2*>(xin);
    float2* xout2 = reinterpret_cast<float2*>(xout);
    #pragma unroll
    for (int r = 0; r < 8; r++) {
        int row = row0 + rbase + r;
        if (row >= n) break;
        float lo, hi;
        unpack2(aA0[r], lo, hi); float av0 = lo + hi + bA.x;
        unpack2(aA1[r], lo, hi); float av1 = lo + hi + bA.y;
        unpack2(aG0[r], lo, hi); float gv0 = lo + hi + bG.x;
        unpack2(aG1[r], lo, hi); float gv1 = lo + hi + bG.y;
        float2 res = xin2[(size_t)row * 32 + lane];
        float o0 = fmaf(av0, 1.0f / (1.0f + expf(-gv0)), res.x);
        float o1 = fmaf(av1, 1.0f / (1.0f + expf(-gv1)), res.y);
        xout2[(size_t)row * 32 + lane] = make_float2(o0, o1);
    }
}

extern "C" void kernel_launch(void* const* d_in, const int* in_sizes, int n_in,
                              void* d_out, int out_size) {
    // Identify inputs by SIZE:
    //   x: == out_size (6.4M f32); edge_index: largest rest (3.2M i32);
    //   Ws: next (24576 f32); bs: smallest (384 f32)
    const float* x = nullptr; const float* Ws = nullptr; const float* bs = nullptr;
    const int* ei = nullptr;
    int ei_elems = 0, Ws_elems = 0;
    int used[16] = {0};
    for (int i = 0; i < n_in; i++)
        if (!x && in_sizes[i] == out_size) { x = (const float*)d_in[i]; used[i] = 1; break; }
    {
        int best = -1, bsz = -1;
        for (int i = 0; i < n_in; i++)
            if (!used[i] && in_sizes[i] > bsz) { bsz = in_sizes[i]; best = i; }
        ei = (const int*)d_in[best]; ei_elems = bsz; used[best] = 1;
    }
    {
        int best = -1, bsz = -1;
        for (int i = 0; i < n_in; i++)
            if (!used[i] && in_sizes[i] > bsz) { bsz = in_sizes[i]; best = i; }
        Ws = (const float*)d_in[best]; Ws_elems = bsz; used[best] = 1;
    }
    for (int i = 0; i < n_in; i++)
        if (!used[i]) { bs = (const float*)d_in[i]; used[i] = 1; break; }

    const int n = out_size / C_IN;
    const int e = ei_elems / 2;
    const int L = Ws_elems / (C_IN * C_OUT);
    const int* src = ei;
    const int* dst = ei + e;
    const int nb = (n + 1023) / 1024;   // 98 blocks, all resident

    float *x0, *x1;
    cudaGetSymbolAddress((void**)&x0, g_x0);
    cudaGetSymbolAddress((void**)&x1, g_x1);

    // ---- CSR build: 2 launches ----
    csr_scan_kernel<<<nb, 1024>>>(dst, e, n, nb);
    fill_kernel<<<(e + 255) / 256, 256>>>(src, dst, e, n, nb);

    // ---- layers (gemm of layer 0 is launch 4 -> profiled) ----
    const float* xin = x;
    for (int l = 0; l < L; l++) {
        float* xout = (l == L - 1) ? (float*)d_out : ((l & 1) ? x1 : x0);
        agg_kernel<<<(n * 32 + 255) / 256, 256>>>(xin, n);
        gemm_glu_kernel<<<(n + GRPB - 1) / GRPB, 256>>>(
            xin, xout, Ws + (size_t)l * C_IN * C_OUT, bs + (size_t)l * C_OUT, n);
        xin = xout;
    }
}